// round 5
// baseline (speedup 1.0000x reference)
#include <cuda_runtime.h>
#include <cuda_bf16.h>
#include <cstdint>

#define B_ROWS 4096
#define S_ROWS 2048
#define DDIM   2496
#define DPAD   2560          // int8 row stride (zero-padded), 20 x 128B
#define DPAD_U32 (DPAD / 4)  // 640

// ---------------- device scratch (allocation-free rule) ----------------
__device__ __align__(16) int8_t g_Xq[(size_t)B_ROWS * DPAD];
__device__ __align__(16) int8_t g_Mq[(size_t)S_ROWS * DPAD];
__device__ float g_xsq[B_ROWS];
__device__ float g_msq[S_ROWS];

// ---------------- helpers ----------------
__device__ __forceinline__ uint32_t smem_to_u32(const void* p) {
    uint32_t a;
    asm("{ .reg .u64 t; cvta.to.shared.u64 t, %1; cvt.u32.u64 %0, t; }" : "=r"(a) : "l"(p));
    return a;
}
#define SWZ_C(row, c) ((c) ^ (((row) & 7) << 4))   // SW128 swizzle within 128B rows

#define CP_ASYNC16(dst, src) \
    asm volatile("cp.async.cg.shared.global [%0], [%1], 16;" :: "r"(dst), "l"(src))
#define CP_COMMIT() asm volatile("cp.async.commit_group;" ::: "memory")
#define CP_WAIT1()  asm volatile("cp.async.wait_group 1;" ::: "memory")

#define LDSM_X4(r, addr) \
    asm volatile("ldmatrix.sync.aligned.m8n8.x4.shared.b16 {%0,%1,%2,%3}, [%4];" \
        : "=r"((r)[0]), "=r"((r)[1]), "=r"((r)[2]), "=r"((r)[3]) : "r"(addr))

#define IMMA16832(d, a, b0, b1) \
    asm volatile("mma.sync.aligned.m16n8k32.row.col.s32.s8.s8.s32 " \
        "{%0,%1,%2,%3}, {%4,%5,%6,%7}, {%8,%9}, {%0,%1,%2,%3};" \
        : "+r"((d)[0]), "+r"((d)[1]), "+r"((d)[2]), "+r"((d)[3]) \
        : "r"((a)[0]), "r"((a)[1]), "r"((a)[2]), "r"((a)[3]), "r"(b0), "r"(b1))

// ---------------------------------------------------------------------------
// Fused convert: warp-per-row. fp32 -> s8 (q = round(v*127)) + exact fp32
// sq-norm of the ORIGINAL values. Rows [0,4096)->X, [4096,6144)->M.
// ---------------------------------------------------------------------------
#define CONV_WPB 8
__global__ __launch_bounds__(256, 4)
void convert_fused(const float* __restrict__ X, const float* __restrict__ M) {
    const int lane  = threadIdx.x & 31;
    const int gwarp = blockIdx.x * CONV_WPB + (threadIdx.x >> 5);

    const float* src;
    int8_t* dst;
    float* sqv;
    if (gwarp < B_ROWS) {
        src = X + (size_t)gwarp * DDIM;
        dst = g_Xq + (size_t)gwarp * DPAD;
        sqv = &g_xsq[gwarp];
    } else {
        const int row = gwarp - B_ROWS;
        src = M + (size_t)row * DDIM;
        dst = g_Mq + (size_t)row * DPAD;
        sqv = &g_msq[row];
    }

    const float4* s4  = reinterpret_cast<const float4*>(src);
    uint32_t*     d32 = reinterpret_cast<uint32_t*>(dst);

    float acc = 0.f;
    const int n4 = DDIM / 4;  // 624
    #pragma unroll 4
    for (int i = lane; i < n4; i += 32) {
        float4 f = s4[i];
        acc = fmaf(f.x, f.x, acc);
        acc = fmaf(f.y, f.y, acc);
        acc = fmaf(f.z, f.z, acc);
        acc = fmaf(f.w, f.w, acc);
        const int qx = __float2int_rn(f.x * 127.0f);
        const int qy = __float2int_rn(f.y * 127.0f);
        const int qz = __float2int_rn(f.z * 127.0f);
        const int qw = __float2int_rn(f.w * 127.0f);
        d32[i] = (uint32_t)(qx & 0xFF) | ((uint32_t)(qy & 0xFF) << 8) |
                 ((uint32_t)(qz & 0xFF) << 16) | ((uint32_t)(qw & 0xFF) << 24);
    }
    // zero the 64-byte k-padding (u32 indices 624..639)
    if (lane < 16) d32[624 + lane] = 0u;

    #pragma unroll
    for (int o = 16; o > 0; o >>= 1) acc += __shfl_down_sync(0xFFFFFFFFu, acc, o);
    if (lane == 0) *sqv = acc;
}

// ---------------------------------------------------------------------------
// int8 IMMA GEMM, CTA tile 128x128, BK=128 s8 (128B rows), 4 warps (2x2),
// warp tile 64x64, SW128 swizzle + ldmatrix(b16-on-s8), cp.async 3 stages,
// 2 CTAs/SM. Epilogue: out = (xsq+msq)*(-1/500) + cross_int * (0.004/127^2)
// ---------------------------------------------------------------------------
#define BM 128
#define BN 128
#define NSTAGE 3
#define NT (DPAD / 128)                 // 20
#define A_BYTES (BM * 128)              // 16384
#define B_BYTES (BN * 128)              // 16384
#define STAGE_BYTES (A_BYTES + B_BYTES) // 32768
#define K1 2.4800049e-07f               // 0.004 / 16129

__global__ __launch_bounds__(128, 2)
void gemm_sqdist_imma(float* __restrict__ out) {
    extern __shared__ char dyn_smem[];
    __shared__ float s_xsq[BM];   // pre-scaled by -2e-3
    __shared__ float s_msq[BN];   // pre-scaled by -2e-3

    const int tid  = threadIdx.x;
    const int lane = tid & 31;
    const int warp = tid >> 5;
    const int wm   = warp & 1;
    const int wn   = warp >> 1;

    const int bm = blockIdx.y * BM;
    const int bn = blockIdx.x * BN;

    const uint32_t dbase = (smem_to_u32(dyn_smem) + 1023u) & ~1023u;
    uint32_t sA[NSTAGE], sB[NSTAGE];
    #pragma unroll
    for (int s = 0; s < NSTAGE; s++) {
        sA[s] = dbase + s * STAGE_BYTES;
        sB[s] = sA[s] + A_BYTES;
    }

    s_xsq[tid] = g_xsq[bm + tid] * -2.0e-3f;
    s_msq[tid] = g_msq[bn + tid] * -2.0e-3f;

    const int8_t* gA = g_Xq + (size_t)bm * DPAD;
    const int8_t* gB = g_Mq + (size_t)bn * DPAD;

    // stage loader: 128 rows x 8 chunks(16B) each for A and B, 128 threads
    auto load_stage = [&](int kt, int buf) {
        const int kb = kt * 128;  // byte offset along k
        #pragma unroll
        for (int q = 0; q < 8; q++) {
            const int item = q * 128 + tid;
            const int row = item >> 3, i = item & 7;
            const uint32_t dst = sA[buf] + row * 128 + SWZ_C(row, i * 16);
            CP_ASYNC16(dst, gA + (size_t)row * DPAD + kb + i * 16);
        }
        #pragma unroll
        for (int q = 0; q < 8; q++) {
            const int item = q * 128 + tid;
            const int row = item >> 3, i = item & 7;
            const uint32_t dst = sB[buf] + row * 128 + SWZ_C(row, i * 16);
            CP_ASYNC16(dst, gB + (size_t)row * DPAD + kb + i * 16);
        }
    };

    // ldmatrix lane addressing (16B half-k units — same arithmetic as bf16)
    const int a_row  = (lane & 7) + ((lane >> 3) & 1) * 8;
    const int a_koff = ((lane >> 4) & 1) * 16;
    const uint32_t a_base_off = (uint32_t)(wm * 64 + a_row) * 128;
    const int a_xm = (a_row & 7) << 4;
    const int b_row  = (lane & 7) + ((lane >> 4) & 1) * 8;
    const int b_koff = ((lane >> 3) & 1) * 16;
    const uint32_t b_base_off = (uint32_t)(wn * 64 + b_row) * 128;
    const int b_xm = (b_row & 7) << 4;

    int c[4][8][4];
    #pragma unroll
    for (int mi = 0; mi < 4; mi++)
        #pragma unroll
        for (int ni = 0; ni < 8; ni++)
            #pragma unroll
            for (int e = 0; e < 4; e++) c[mi][ni][e] = 0;

    load_stage(0, 0); CP_COMMIT();
    load_stage(1, 1); CP_COMMIT();
    CP_WAIT1();
    __syncthreads();

    for (int kt = 0; kt < NT; kt++) {
        const int buf = kt % NSTAGE;

        if (kt + 2 < NT) load_stage(kt + 2, (kt + 2) % NSTAGE);
        CP_COMMIT();

        const uint32_t aw = sA[buf] + a_base_off;
        const uint32_t bw = sB[buf] + b_base_off;

        #pragma unroll
        for (int q = 0; q < 4; q++) {   // k32 steps within 128B
            const uint32_t aq = (uint32_t)((q * 32 + a_koff) ^ a_xm);
            const uint32_t bq = (uint32_t)((q * 32 + b_koff) ^ b_xm);
            uint32_t a[4][4];
            #pragma unroll
            for (int mi = 0; mi < 4; mi++) LDSM_X4(a[mi], aw + mi * 2048 + aq);
            uint32_t b[4][4];
            #pragma unroll
            for (int nj = 0; nj < 4; nj++) LDSM_X4(b[nj], bw + nj * 2048 + bq);
            #pragma unroll
            for (int mi = 0; mi < 4; mi++)
                #pragma unroll
                for (int ni = 0; ni < 8; ni++)
                    IMMA16832(c[mi][ni], a[mi], b[ni >> 1][(ni & 1) * 2], b[ni >> 1][(ni & 1) * 2 + 1]);
        }

        CP_WAIT1();
        __syncthreads();
    }

    // ---- fused epilogue: out = xs_s + ms_s + cross_int * K1 ----
    const int gid = lane >> 2, tig = lane & 3;

    #pragma unroll
    for (int mi = 0; mi < 4; mi++) {
        const int r0 = wm * 64 + mi * 16 + gid;
        const float xs0 = s_xsq[r0];
        const float xs1 = s_xsq[r0 + 8];
        float* o0 = out + (size_t)(bm + r0) * S_ROWS + bn;
        float* o1 = o0 + (size_t)8 * S_ROWS;
        #pragma unroll
        for (int ni = 0; ni < 8; ni++) {
            const int col = wn * 64 + ni * 8 + tig * 2;
            const float ms0 = s_msq[col];
            const float ms1 = s_msq[col + 1];
            float2 v0, v1;
            v0.x = fmaf((float)c[mi][ni][0], K1, xs0 + ms0);
            v0.y = fmaf((float)c[mi][ni][1], K1, xs0 + ms1);
            v1.x = fmaf((float)c[mi][ni][2], K1, xs1 + ms0);
            v1.y = fmaf((float)c[mi][ni][3], K1, xs1 + ms1);
            *reinterpret_cast<float2*>(o0 + col) = v0;
            *reinterpret_cast<float2*>(o1 + col) = v1;
        }
    }
}

// ---------------------------------------------------------------------------
extern "C" void kernel_launch(void* const* d_in, const int* in_sizes, int n_in,
                              void* d_out, int out_size) {
    const float* observation        = (const float*)d_in[0];  // [4096, 2496]
    const float* observation_matrix = (const float*)d_in[1];  // [2048, 2496]
    float* out = (float*)d_out;                                // [4096, 2048]

    const int conv_blocks = (B_ROWS + S_ROWS) / CONV_WPB;  // 768
    convert_fused<<<conv_blocks, 256>>>(observation, observation_matrix);

    const int dyn_bytes = NSTAGE * STAGE_BYTES + 1024;  // 99328
    cudaFuncSetAttribute(gemm_sqdist_imma, cudaFuncAttributeMaxDynamicSharedMemorySize, dyn_bytes);
    dim3 grid(S_ROWS / BN, B_ROWS / BM);  // (16, 32) = 512 CTAs
    gemm_sqdist_imma<<<grid, 128, dyn_bytes>>>(out);
}

// round 6
// speedup vs baseline: 2.7916x; 2.7916x over previous
#include <cuda_runtime.h>
#include <cuda_bf16.h>
#include <cstdint>

#define B_ROWS 4096
#define S_ROWS 2048
#define DDIM   2496

// ---------------- device scratch (allocation-free rule) ----------------
__device__ __align__(16) __nv_bfloat16 g_Xb[(size_t)B_ROWS * DDIM];
__device__ __align__(16) __nv_bfloat16 g_Mb[(size_t)S_ROWS * DDIM];
__device__ float g_xsq[B_ROWS];
__device__ float g_msq[S_ROWS];

// ---------------- helpers ----------------
__device__ __forceinline__ uint32_t smem_to_u32(const void* p) {
    uint32_t a;
    asm("{ .reg .u64 t; cvta.to.shared.u64 t, %1; cvt.u32.u64 %0, t; }" : "=r"(a) : "l"(p));
    return a;
}
#define SWZ_C(row, c) ((c) ^ (((row) & 7) << 4))   // SW128 swizzle within 128B rows

#define CP_ASYNC16(dst, src) \
    asm volatile("cp.async.cg.shared.global [%0], [%1], 16;" :: "r"(dst), "l"(src))
#define CP_COMMIT() asm volatile("cp.async.commit_group;" ::: "memory")
#define CP_WAIT1()  asm volatile("cp.async.wait_group 1;" ::: "memory")

#define LDSM_X4(r, addr) \
    asm volatile("ldmatrix.sync.aligned.m8n8.x4.shared.b16 {%0,%1,%2,%3}, [%4];" \
        : "=r"((r)[0]), "=r"((r)[1]), "=r"((r)[2]), "=r"((r)[3]) : "r"(addr))

#define MMA16816(d, a, b0, b1) \
    asm volatile("mma.sync.aligned.m16n8k16.row.col.f32.bf16.bf16.f32 " \
        "{%0,%1,%2,%3}, {%4,%5,%6,%7}, {%8,%9}, {%0,%1,%2,%3};" \
        : "+f"((d)[0]), "+f"((d)[1]), "+f"((d)[2]), "+f"((d)[3]) \
        : "r"((a)[0]), "r"((a)[1]), "r"((a)[2]), "r"((a)[3]), "r"(b0), "r"(b1))

// ---------------------------------------------------------------------------
// Fused convert: warp-per-row, both tensors in one launch.
// Rows [0,4096) -> X, rows [4096,6144) -> M. fp32 -> bf16 + fp32 sq-norm.
// ---------------------------------------------------------------------------
#define CONV_WPB 8
__global__ __launch_bounds__(256, 4)
void convert_fused(const float* __restrict__ X, const float* __restrict__ M) {
    const int lane  = threadIdx.x & 31;
    const int gwarp = blockIdx.x * CONV_WPB + (threadIdx.x >> 5);

    const float* src;
    __nv_bfloat16* dst;
    float* sqv;
    if (gwarp < B_ROWS) {
        src = X + (size_t)gwarp * DDIM;
        dst = g_Xb + (size_t)gwarp * DDIM;
        sqv = &g_xsq[gwarp];
    } else {
        const int row = gwarp - B_ROWS;
        src = M + (size_t)row * DDIM;
        dst = g_Mb + (size_t)row * DDIM;
        sqv = &g_msq[row];
    }

    const float4* s4 = reinterpret_cast<const float4*>(src);
    uint2*        d2 = reinterpret_cast<uint2*>(dst);

    float acc = 0.f;
    const int n4 = DDIM / 4;  // 624
    #pragma unroll 4
    for (int i = lane; i < n4; i += 32) {
        float4 f = s4[i];
        acc = fmaf(f.x, f.x, acc);
        acc = fmaf(f.y, f.y, acc);
        acc = fmaf(f.z, f.z, acc);
        acc = fmaf(f.w, f.w, acc);
        __nv_bfloat162 lo = __floats2bfloat162_rn(f.x, f.y);
        __nv_bfloat162 hi = __floats2bfloat162_rn(f.z, f.w);
        uint2 u;
        u.x = *reinterpret_cast<unsigned int*>(&lo);
        u.y = *reinterpret_cast<unsigned int*>(&hi);
        d2[i] = u;
    }
    #pragma unroll
    for (int o = 16; o > 0; o >>= 1) acc += __shfl_down_sync(0xFFFFFFFFu, acc, o);
    if (lane == 0) *sqv = acc;
}

// ---------------------------------------------------------------------------
// bf16 mma.sync GEMM, CTA tile 128x128, BK=64, 8 warps (2Mx4N),
// warp tile 64x32 -> 4 warps/SMSP at 2 CTAs/SM (16 warps/SM).
// SW128 swizzle + ldmatrix, cp.async 3-stage pipeline.
// Fused epilogue: out = (xsq + msq - 2*dot) * (-1/500)
// ---------------------------------------------------------------------------
#define BM 128
#define BN 128
#define BK 64
#define NSTAGE 3
#define NT (DDIM / BK)                  // 39
#define A_BYTES (BM * 128)              // 16384
#define B_BYTES (BN * 128)              // 16384
#define STAGE_BYTES (A_BYTES + B_BYTES) // 32768

__global__ __launch_bounds__(256, 2)
void gemm_sqdist_mma(float* __restrict__ out) {
    extern __shared__ char dyn_smem[];
    __shared__ float s_xsq[BM];
    __shared__ float s_msq[BN];

    const int tid  = threadIdx.x;
    const int lane = tid & 31;
    const int warp = tid >> 5;
    const int wm   = warp >> 2;  // 0..1 -> M rows [wm*64, wm*64+64)
    const int wn   = warp & 3;   // 0..3 -> N cols [wn*32, wn*32+32)

    const int bm = blockIdx.y * BM;
    const int bn = blockIdx.x * BN;

    const uint32_t dbase = (smem_to_u32(dyn_smem) + 1023u) & ~1023u;
    uint32_t sA[NSTAGE], sB[NSTAGE];
    #pragma unroll
    for (int s = 0; s < NSTAGE; s++) {
        sA[s] = dbase + s * STAGE_BYTES;
        sB[s] = sA[s] + A_BYTES;
    }

    if (tid < BM) s_xsq[tid] = g_xsq[bm + tid];
    else          s_msq[tid - BM] = g_msq[bn + (tid - BM)];

    const __nv_bfloat16* gA = g_Xb + (size_t)bm * DDIM;
    const __nv_bfloat16* gB = g_Mb + (size_t)bn * DDIM;

    // ---- stage loader: A 1024 chunks(16B) + B 1024, 256 threads, 4 each ----
    auto load_stage = [&](int kt, int buf) {
        const int kb = kt * 8;  // uint4 index at row start
        #pragma unroll
        for (int q = 0; q < 4; q++) {
            const int item = q * 256 + tid;
            const int row = item >> 3, i = item & 7;
            const uint32_t dst = sA[buf] + row * 128 + SWZ_C(row, i * 16);
            CP_ASYNC16(dst, gA + (size_t)row * DDIM + (size_t)(kb + i) * 8);
        }
        #pragma unroll
        for (int q = 0; q < 4; q++) {
            const int item = q * 256 + tid;
            const int row = item >> 3, i = item & 7;
            const uint32_t dst = sB[buf] + row * 128 + SWZ_C(row, i * 16);
            CP_ASYNC16(dst, gB + (size_t)row * DDIM + (size_t)(kb + i) * 8);
        }
    };

    // ---- per-lane ldmatrix addressing ----
    const int a_row  = (lane & 7) + ((lane >> 3) & 1) * 8;
    const int a_koff = ((lane >> 4) & 1) * 16;
    const uint32_t a_base_off = (uint32_t)(wm * 64 + a_row) * 128;
    const int a_xm = (a_row & 7) << 4;
    const int b_row  = (lane & 7) + ((lane >> 4) & 1) * 8;
    const int b_koff = ((lane >> 3) & 1) * 16;
    const uint32_t b_base_off = (uint32_t)(wn * 32 + b_row) * 128;
    const int b_xm = (b_row & 7) << 4;

    float c[4][4][4];
    #pragma unroll
    for (int mi = 0; mi < 4; mi++)
        #pragma unroll
        for (int ni = 0; ni < 4; ni++)
            #pragma unroll
            for (int e = 0; e < 4; e++) c[mi][ni][e] = 0.f;

    // ---- pipeline prologue ----
    load_stage(0, 0); CP_COMMIT();
    load_stage(1, 1); CP_COMMIT();
    CP_WAIT1();
    __syncthreads();

    for (int kt = 0; kt < NT; kt++) {
        const int buf = kt % NSTAGE;

        if (kt + 2 < NT) load_stage(kt + 2, (kt + 2) % NSTAGE);
        CP_COMMIT();

        const uint32_t aw = sA[buf] + a_base_off;
        const uint32_t bw = sB[buf] + b_base_off;

        #pragma unroll
        for (int q = 0; q < 4; q++) {   // k16 steps within BK=64
            const uint32_t aq = (uint32_t)((q * 32 + a_koff) ^ a_xm);
            const uint32_t bq = (uint32_t)((q * 32 + b_koff) ^ b_xm);
            uint32_t a[4][4];
            #pragma unroll
            for (int mi = 0; mi < 4; mi++) LDSM_X4(a[mi], aw + mi * 2048 + aq);
            uint32_t b[2][4];
            #pragma unroll
            for (int nj = 0; nj < 2; nj++) LDSM_X4(b[nj], bw + nj * 2048 + bq);
            #pragma unroll
            for (int mi = 0; mi < 4; mi++)
                #pragma unroll
                for (int ni = 0; ni < 4; ni++)
                    MMA16816(c[mi][ni], a[mi], b[ni >> 1][(ni & 1) * 2], b[ni >> 1][(ni & 1) * 2 + 1]);
        }

        CP_WAIT1();
        __syncthreads();
    }

    // ---- fused epilogue ----
    const int gid = lane >> 2, tig = lane & 3;
    const float scale = -2.0e-3f;  // 1/(-500)

    #pragma unroll
    for (int mi = 0; mi < 4; mi++) {
        const int r0 = wm * 64 + mi * 16 + gid;
        const float xs0 = s_xsq[r0];
        const float xs1 = s_xsq[r0 + 8];
        float* o0 = out + (size_t)(bm + r0) * S_ROWS + bn;
        float* o1 = o0 + (size_t)8 * S_ROWS;
        #pragma unroll
        for (int ni = 0; ni < 4; ni++) {
            const int col = wn * 32 + ni * 8 + tig * 2;
            const float ms0 = s_msq[col];
            const float ms1 = s_msq[col + 1];
            float2 v0, v1;
            v0.x = (xs0 + ms0 - 2.f * c[mi][ni][0]) * scale;
            v0.y = (xs0 + ms1 - 2.f * c[mi][ni][1]) * scale;
            v1.x = (xs1 + ms0 - 2.f * c[mi][ni][2]) * scale;
            v1.y = (xs1 + ms1 - 2.f * c[mi][ni][3]) * scale;
            *reinterpret_cast<float2*>(o0 + col) = v0;
            *reinterpret_cast<float2*>(o1 + col) = v1;
        }
    }
}

// ---------------------------------------------------------------------------
extern "C" void kernel_launch(void* const* d_in, const int* in_sizes, int n_in,
                              void* d_out, int out_size) {
    const float* observation        = (const float*)d_in[0];  // [4096, 2496]
    const float* observation_matrix = (const float*)d_in[1];  // [2048, 2496]
    float* out = (float*)d_out;                                // [4096, 2048]

    const int conv_blocks = (B_ROWS + S_ROWS) / CONV_WPB;  // 768
    convert_fused<<<conv_blocks, 256>>>(observation, observation_matrix);

    const int dyn_bytes = NSTAGE * STAGE_BYTES + 1024;  // 99328
    cudaFuncSetAttribute(gemm_sqdist_mma, cudaFuncAttributeMaxDynamicSharedMemorySize, dyn_bytes);
    dim3 grid(S_ROWS / BN, B_ROWS / BM);  // (16, 32) = 512 CTAs
    gemm_sqdist_mma<<<grid, 256, dyn_bytes>>>(out);
}

// round 7
// speedup vs baseline: 3.2779x; 1.1742x over previous
#include <cuda_runtime.h>
#include <cuda_bf16.h>
#include <cstdint>

#define B_ROWS 4096
#define S_ROWS 2048
#define DDIM   2496

// ---------------- device scratch (allocation-free rule) ----------------
__device__ __align__(16) __nv_bfloat16 g_Xb[(size_t)B_ROWS * DDIM];
__device__ __align__(16) __nv_bfloat16 g_Mb[(size_t)S_ROWS * DDIM];
__device__ float g_xsq[B_ROWS];
__device__ float g_msq[S_ROWS];

// ---------------- helpers ----------------
__device__ __forceinline__ uint32_t smem_to_u32(const void* p) {
    uint32_t a;
    asm("{ .reg .u64 t; cvta.to.shared.u64 t, %1; cvt.u32.u64 %0, t; }" : "=r"(a) : "l"(p));
    return a;
}
#define SWZ_C(row, c) ((c) ^ (((row) & 7) << 4))   // SW128 swizzle within 128B rows

#define CP_ASYNC16(dst, src) \
    asm volatile("cp.async.cg.shared.global [%0], [%1], 16;" :: "r"(dst), "l"(src))
#define CP_COMMIT() asm volatile("cp.async.commit_group;" ::: "memory")
#define CP_WAIT1()  asm volatile("cp.async.wait_group 1;" ::: "memory")

#define LDSM_X4(r, addr) \
    asm volatile("ldmatrix.sync.aligned.m8n8.x4.shared.b16 {%0,%1,%2,%3}, [%4];" \
        : "=r"((r)[0]), "=r"((r)[1]), "=r"((r)[2]), "=r"((r)[3]) : "r"(addr))

#define MMA16816(d, a, b0, b1) \
    asm volatile("mma.sync.aligned.m16n8k16.row.col.f32.bf16.bf16.f32 " \
        "{%0,%1,%2,%3}, {%4,%5,%6,%7}, {%8,%9}, {%0,%1,%2,%3};" \
        : "+f"((d)[0]), "+f"((d)[1]), "+f"((d)[2]), "+f"((d)[3]) \
        : "r"((a)[0]), "r"((a)[1]), "r"((a)[2]), "r"((a)[3]), "r"(b0), "r"(b1))

// ---------------------------------------------------------------------------
// Fused convert: warp-per-row, both tensors in one launch.
// ---------------------------------------------------------------------------
#define CONV_WPB 8
__global__ __launch_bounds__(256, 4)
void convert_fused(const float* __restrict__ X, const float* __restrict__ M) {
    const int lane  = threadIdx.x & 31;
    const int gwarp = blockIdx.x * CONV_WPB + (threadIdx.x >> 5);

    const float* src;
    __nv_bfloat16* dst;
    float* sqv;
    if (gwarp < B_ROWS) {
        src = X + (size_t)gwarp * DDIM;
        dst = g_Xb + (size_t)gwarp * DDIM;
        sqv = &g_xsq[gwarp];
    } else {
        const int row = gwarp - B_ROWS;
        src = M + (size_t)row * DDIM;
        dst = g_Mb + (size_t)row * DDIM;
        sqv = &g_msq[row];
    }

    const float4* s4 = reinterpret_cast<const float4*>(src);
    uint2*        d2 = reinterpret_cast<uint2*>(dst);

    float acc = 0.f;
    const int n4 = DDIM / 4;  // 624
    #pragma unroll 4
    for (int i = lane; i < n4; i += 32) {
        float4 f = s4[i];
        acc = fmaf(f.x, f.x, acc);
        acc = fmaf(f.y, f.y, acc);
        acc = fmaf(f.z, f.z, acc);
        acc = fmaf(f.w, f.w, acc);
        __nv_bfloat162 lo = __floats2bfloat162_rn(f.x, f.y);
        __nv_bfloat162 hi = __floats2bfloat162_rn(f.z, f.w);
        uint2 u;
        u.x = *reinterpret_cast<unsigned int*>(&lo);
        u.y = *reinterpret_cast<unsigned int*>(&hi);
        d2[i] = u;
    }
    #pragma unroll
    for (int o = 16; o > 0; o >>= 1) acc += __shfl_down_sync(0xFFFFFFFFu, acc, o);
    if (lane == 0) *sqv = acc;
}

// ---------------------------------------------------------------------------
// bf16 mma.sync GEMM, CTA 128x128, BK=64, 4 warps (2x2), warp tile 64x64,
// 2 CTAs/SM. SW128 + ldmatrix, cp.async 3-stage pipeline, register-level
// fragment pipelining across k16 steps (B double-buffered, A just-in-time).
// Fused epilogue: out = fmaf(dot, 4e-3, -(xsq+msq)*2e-3)
// ---------------------------------------------------------------------------
#define BM 128
#define BN 128
#define BK 64
#define NSTAGE 3
#define NT (DDIM / BK)                  // 39
#define A_BYTES (BM * 128)              // 16384
#define B_BYTES (BN * 128)              // 16384
#define STAGE_BYTES (A_BYTES + B_BYTES) // 32768

__global__ __launch_bounds__(128, 2)
void gemm_sqdist_mma(float* __restrict__ out) {
    extern __shared__ char dyn_smem[];
    __shared__ float s_xsq[BM];   // pre-scaled by -2e-3
    __shared__ float s_msq[BN];   // pre-scaled by -2e-3

    const int tid  = threadIdx.x;
    const int lane = tid & 31;
    const int warp = tid >> 5;
    const int wm   = warp & 1;
    const int wn   = warp >> 1;

    const int bm = blockIdx.y * BM;
    const int bn = blockIdx.x * BN;

    const uint32_t dbase = (smem_to_u32(dyn_smem) + 1023u) & ~1023u;
    uint32_t sA[NSTAGE], sB[NSTAGE];
    #pragma unroll
    for (int s = 0; s < NSTAGE; s++) {
        sA[s] = dbase + s * STAGE_BYTES;
        sB[s] = sA[s] + A_BYTES;
    }

    s_xsq[tid] = g_xsq[bm + tid] * -2.0e-3f;
    s_msq[tid] = g_msq[bn + tid] * -2.0e-3f;

    const __nv_bfloat16* gA = g_Xb + (size_t)bm * DDIM;
    const __nv_bfloat16* gB = g_Mb + (size_t)bn * DDIM;

    auto load_stage = [&](int kt, uint32_t dstA, uint32_t dstB) {
        const int kb = kt * 8;  // uint4 index at row start
        #pragma unroll
        for (int q = 0; q < 8; q++) {
            const int item = q * 128 + tid;
            const int row = item >> 3, i = item & 7;
            CP_ASYNC16(dstA + row * 128 + SWZ_C(row, i * 16),
                       gA + (size_t)row * DDIM + (size_t)(kb + i) * 8);
        }
        #pragma unroll
        for (int q = 0; q < 8; q++) {
            const int item = q * 128 + tid;
            const int row = item >> 3, i = item & 7;
            CP_ASYNC16(dstB + row * 128 + SWZ_C(row, i * 16),
                       gB + (size_t)row * DDIM + (size_t)(kb + i) * 8);
        }
    };

    // ---- per-lane ldmatrix addressing ----
    const int a_row  = (lane & 7) + ((lane >> 3) & 1) * 8;
    const int a_koff = ((lane >> 4) & 1) * 16;
    const uint32_t a_base_off = (uint32_t)(wm * 64 + a_row) * 128;
    const int a_xm = (a_row & 7) << 4;
    const int b_row  = (lane & 7) + ((lane >> 4) & 1) * 8;
    const int b_koff = ((lane >> 3) & 1) * 16;
    const uint32_t b_base_off = (uint32_t)(wn * 64 + b_row) * 128;
    const int b_xm = (b_row & 7) << 4;

    float c[4][8][4];
    #pragma unroll
    for (int mi = 0; mi < 4; mi++)
        #pragma unroll
        for (int ni = 0; ni < 8; ni++)
            #pragma unroll
            for (int e = 0; e < 4; e++) c[mi][ni][e] = 0.f;

    // ---- pipeline prologue ----
    load_stage(0, sA[0], sB[0]); CP_COMMIT();
    load_stage(1, sA[1], sB[1]); CP_COMMIT();
    CP_WAIT1();
    __syncthreads();

    #pragma unroll 3
    for (int kt = 0; kt < NT; kt++) {
        const int buf = kt % NSTAGE;

        if (kt + 2 < NT) {
            const int nb = (kt + 2) % NSTAGE;
            load_stage(kt + 2, sA[nb], sB[nb]);
        }
        CP_COMMIT();

        const uint32_t aw = sA[buf] + a_base_off;
        const uint32_t bw = sB[buf] + b_base_off;

        // ---- register-pipelined k16 steps ----
        uint32_t a[4][4];       // A frags, just-in-time reload per mi
        uint32_t b[2][4][4];    // B frags, double-buffered across q

        {   // q = 0 preload
            const uint32_t aq = (uint32_t)(a_koff ^ a_xm);
            const uint32_t bq = (uint32_t)(b_koff ^ b_xm);
            #pragma unroll
            for (int mi = 0; mi < 4; mi++) LDSM_X4(a[mi], aw + mi * 2048 + aq);
            #pragma unroll
            for (int nj = 0; nj < 4; nj++) LDSM_X4(b[0][nj], bw + nj * 2048 + bq);
        }

        #pragma unroll
        for (int q = 0; q < 4; q++) {
            const int cb = q & 1;
            // prefetch next q's B frags into the other buffer
            if (q < 3) {
                const uint32_t bq = (uint32_t)(((q + 1) * 32 + b_koff) ^ b_xm);
                #pragma unroll
                for (int nj = 0; nj < 4; nj++) LDSM_X4(b[cb ^ 1][nj], bw + nj * 2048 + bq);
            }
            #pragma unroll
            for (int mi = 0; mi < 4; mi++) {
                #pragma unroll
                for (int ni = 0; ni < 8; ni++)
                    MMA16816(c[mi][ni], a[mi],
                             b[cb][ni >> 1][(ni & 1) * 2], b[cb][ni >> 1][(ni & 1) * 2 + 1]);
                // a[mi] consumed for this q -> reload for next q
                if (q < 3) {
                    const uint32_t aq = (uint32_t)(((q + 1) * 32 + a_koff) ^ a_xm);
                    LDSM_X4(a[mi], aw + mi * 2048 + aq);
                }
            }
        }

        CP_WAIT1();
        __syncthreads();
    }

    // ---- fused epilogue: out = fmaf(dot, 4e-3, xs_s + ms_s) ----
    const int gid = lane >> 2, tig = lane & 3;
    const float k4 = 4.0e-3f;  // 2/500

    #pragma unroll
    for (int mi = 0; mi < 4; mi++) {
        const int r0 = wm * 64 + mi * 16 + gid;
        const float xs0 = s_xsq[r0];
        const float xs1 = s_xsq[r0 + 8];
        float* o0 = out + (size_t)(bm + r0) * S_ROWS + bn;
        float* o1 = o0 + (size_t)8 * S_ROWS;
        #pragma unroll
        for (int ni = 0; ni < 8; ni++) {
            const int col = wn * 64 + ni * 8 + tig * 2;
            const float ms0 = s_msq[col];
            const float ms1 = s_msq[col + 1];
            float2 v0, v1;
            v0.x = fmaf(c[mi][ni][0], k4, xs0 + ms0);
            v0.y = fmaf(c[mi][ni][1], k4, xs0 + ms1);
            v1.x = fmaf(c[mi][ni][2], k4, xs1 + ms0);
            v1.y = fmaf(c[mi][ni][3], k4, xs1 + ms1);
            *reinterpret_cast<float2*>(o0 + col) = v0;
            *reinterpret_cast<float2*>(o1 + col) = v1;
        }
    }
}

// ---------------------------------------------------------------------------
extern "C" void kernel_launch(void* const* d_in, const int* in_sizes, int n_in,
                              void* d_out, int out_size) {
    const float* observation        = (const float*)d_in[0];  // [4096, 2496]
    const float* observation_matrix = (const float*)d_in[1];  // [2048, 2496]
    float* out = (float*)d_out;                                // [4096, 2048]

    const int conv_blocks = (B_ROWS + S_ROWS) / CONV_WPB;  // 768
    convert_fused<<<conv_blocks, 256>>>(observation, observation_matrix);

    const int dyn_bytes = NSTAGE * STAGE_BYTES + 1024;  // 99328
    cudaFuncSetAttribute(gemm_sqdist_mma, cudaFuncAttributeMaxDynamicSharedMemorySize, dyn_bytes);
    dim3 grid(S_ROWS / BN, B_ROWS / BM);  // (16, 32) = 512 CTAs
    gemm_sqdist_mma<<<grid, 128, dyn_bytes>>>(out);
}

// round 8
// speedup vs baseline: 3.3529x; 1.0229x over previous
#include <cuda_runtime.h>
#include <cuda_bf16.h>
#include <cstdint>

#define B_ROWS 4096
#define S_ROWS 2048
#define DDIM   2496

// ---------------- device scratch (allocation-free rule) ----------------
__device__ __align__(16) __nv_bfloat16 g_Xb[(size_t)B_ROWS * DDIM];
__device__ __align__(16) __nv_bfloat16 g_Mb[(size_t)S_ROWS * DDIM];
__device__ float g_xsq[B_ROWS];
__device__ float g_msq[S_ROWS];

// ---------------- helpers ----------------
__device__ __forceinline__ uint32_t smem_to_u32(const void* p) {
    uint32_t a;
    asm("{ .reg .u64 t; cvta.to.shared.u64 t, %1; cvt.u32.u64 %0, t; }" : "=r"(a) : "l"(p));
    return a;
}
#define SWZ_C(row, c) ((c) ^ (((row) & 7) << 4))   // SW128 swizzle within 128B rows

#define CP_ASYNC16(dst, src) \
    asm volatile("cp.async.cg.shared.global [%0], [%1], 16;" :: "r"(dst), "l"(src))
#define CP_COMMIT() asm volatile("cp.async.commit_group;" ::: "memory")
#define CP_WAIT1()  asm volatile("cp.async.wait_group 1;" ::: "memory")

#define LDSM_X4(r, addr) \
    asm volatile("ldmatrix.sync.aligned.m8n8.x4.shared.b16 {%0,%1,%2,%3}, [%4];" \
        : "=r"((r)[0]), "=r"((r)[1]), "=r"((r)[2]), "=r"((r)[3]) : "r"(addr))

#define MMA16816(d, a, b0, b1) \
    asm volatile("mma.sync.aligned.m16n8k16.row.col.f32.bf16.bf16.f32 " \
        "{%0,%1,%2,%3}, {%4,%5,%6,%7}, {%8,%9}, {%0,%1,%2,%3};" \
        : "+f"((d)[0]), "+f"((d)[1]), "+f"((d)[2]), "+f"((d)[3]) \
        : "r"((a)[0]), "r"((a)[1]), "r"((a)[2]), "r"((a)[3]), "r"(b0), "r"(b1))

// ---------------------------------------------------------------------------
// Fused convert: warp-per-row, both tensors in one launch.
// ---------------------------------------------------------------------------
#define CONV_WPB 8
__global__ __launch_bounds__(256, 4)
void convert_fused(const float* __restrict__ X, const float* __restrict__ M) {
    const int lane  = threadIdx.x & 31;
    const int gwarp = blockIdx.x * CONV_WPB + (threadIdx.x >> 5);

    const float* src;
    __nv_bfloat16* dst;
    float* sqv;
    if (gwarp < B_ROWS) {
        src = X + (size_t)gwarp * DDIM;
        dst = g_Xb + (size_t)gwarp * DDIM;
        sqv = &g_xsq[gwarp];
    } else {
        const int row = gwarp - B_ROWS;
        src = M + (size_t)row * DDIM;
        dst = g_Mb + (size_t)row * DDIM;
        sqv = &g_msq[row];
    }

    const float4* s4 = reinterpret_cast<const float4*>(src);
    uint2*        d2 = reinterpret_cast<uint2*>(dst);

    float acc = 0.f;
    const int n4 = DDIM / 4;  // 624
    #pragma unroll 4
    for (int i = lane; i < n4; i += 32) {
        float4 f = s4[i];
        acc = fmaf(f.x, f.x, acc);
        acc = fmaf(f.y, f.y, acc);
        acc = fmaf(f.z, f.z, acc);
        acc = fmaf(f.w, f.w, acc);
        __nv_bfloat162 lo = __floats2bfloat162_rn(f.x, f.y);
        __nv_bfloat162 hi = __floats2bfloat162_rn(f.z, f.w);
        uint2 u;
        u.x = *reinterpret_cast<unsigned int*>(&lo);
        u.y = *reinterpret_cast<unsigned int*>(&hi);
        d2[i] = u;
    }
    #pragma unroll
    for (int o = 16; o > 0; o >>= 1) acc += __shfl_down_sync(0xFFFFFFFFu, acc, o);
    if (lane == 0) *sqv = acc;
}

// ---------------------------------------------------------------------------
// bf16 mma.sync GEMM with MIXED tile sizes for wave-tail backfill:
//   bid <  288 : full tile 128x128 (rows [0, 2304))     — wave 1
//   bid >= 288 : half tile  64x128 (rows [2304, 4096))  — dynamic backfill
// Shared templated body: 4 warps, warp tile (MI*16)x64, BK=64, SW128 +
// ldmatrix, cp.async 3 stages, register-pipelined fragments. 2 CTAs/SM.
// Epilogue: out = fmaf(dot, 4e-3, -(xsq+msq)*2e-3)
// ---------------------------------------------------------------------------
#define BN 128
#define BK 64
#define NSTAGE 3
#define NT (DDIM / BK)                   // 39
#define STAGE_STRIDE 32768               // full-tile stage footprint
#define N_FULL 288                       // 18 rows x 16 cols of 128x128
#define N_HALF 448                       // 28 rows x 16 cols of  64x128

template<int MI>   // MI=4: 128-row tile ; MI=2: 64-row tile
__device__ __forceinline__ void tile_body(
    float* __restrict__ out, int bm, int bn, uint32_t dbase, int tid,
    float* s_xsq, float* s_msq)
{
    constexpr int AROWS  = MI * 32;           // 128 or 64
    constexpr int ABYTES = AROWS * 128;

    const int lane = tid & 31;
    const int warp = tid >> 5;
    const int wm   = warp & 1;   // M half within tile
    const int wn   = warp >> 1;  // N half

    uint32_t sA[NSTAGE], sB[NSTAGE];
    #pragma unroll
    for (int s = 0; s < NSTAGE; s++) {
        sA[s] = dbase + s * STAGE_STRIDE;
        sB[s] = sA[s] + ABYTES;
    }

    if (tid < AROWS) s_xsq[tid] = g_xsq[bm + tid] * -2.0e-3f;
    s_msq[tid] = g_msq[bn + tid] * -2.0e-3f;

    const __nv_bfloat16* gA = g_Xb + (size_t)bm * DDIM;
    const __nv_bfloat16* gB = g_Mb + (size_t)bn * DDIM;

    auto load_stage = [&](int kt, uint32_t dstA, uint32_t dstB) {
        const int kb = kt * 8;
        #pragma unroll
        for (int q = 0; q < MI * 2; q++) {   // A: AROWS*8 chunks
            const int item = q * 128 + tid;
            const int row = item >> 3, i = item & 7;
            CP_ASYNC16(dstA + row * 128 + SWZ_C(row, i * 16),
                       gA + (size_t)row * DDIM + (size_t)(kb + i) * 8);
        }
        #pragma unroll
        for (int q = 0; q < 8; q++) {        // B: 1024 chunks
            const int item = q * 128 + tid;
            const int row = item >> 3, i = item & 7;
            CP_ASYNC16(dstB + row * 128 + SWZ_C(row, i * 16),
                       gB + (size_t)row * DDIM + (size_t)(kb + i) * 8);
        }
    };

    // per-lane ldmatrix addressing
    const int a_row  = (lane & 7) + ((lane >> 3) & 1) * 8;
    const int a_koff = ((lane >> 4) & 1) * 16;
    const uint32_t a_base_off = (uint32_t)(wm * (MI * 16) + a_row) * 128;
    const int a_xm = (a_row & 7) << 4;
    const int b_row  = (lane & 7) + ((lane >> 4) & 1) * 8;
    const int b_koff = ((lane >> 3) & 1) * 16;
    const uint32_t b_base_off = (uint32_t)(wn * 64 + b_row) * 128;
    const int b_xm = (b_row & 7) << 4;

    float c[MI][8][4];
    #pragma unroll
    for (int mi = 0; mi < MI; mi++)
        #pragma unroll
        for (int ni = 0; ni < 8; ni++)
            #pragma unroll
            for (int e = 0; e < 4; e++) c[mi][ni][e] = 0.f;

    load_stage(0, sA[0], sB[0]); CP_COMMIT();
    load_stage(1, sA[1], sB[1]); CP_COMMIT();
    CP_WAIT1();
    __syncthreads();

    #pragma unroll 3
    for (int kt = 0; kt < NT; kt++) {
        const int buf = kt % NSTAGE;

        if (kt + 2 < NT) {
            const int nb = (kt + 2) % NSTAGE;
            load_stage(kt + 2, sA[nb], sB[nb]);
        }
        CP_COMMIT();

        const uint32_t aw = sA[buf] + a_base_off;
        const uint32_t bw = sB[buf] + b_base_off;

        uint32_t a[MI][4];
        uint32_t b[2][4][4];

        {   // q = 0 preload
            const uint32_t aq = (uint32_t)(a_koff ^ a_xm);
            const uint32_t bq = (uint32_t)(b_koff ^ b_xm);
            #pragma unroll
            for (int mi = 0; mi < MI; mi++) LDSM_X4(a[mi], aw + mi * 2048 + aq);
            #pragma unroll
            for (int nj = 0; nj < 4; nj++) LDSM_X4(b[0][nj], bw + nj * 2048 + bq);
        }

        #pragma unroll
        for (int q = 0; q < 4; q++) {
            const int cb = q & 1;
            if (q < 3) {
                const uint32_t bq = (uint32_t)(((q + 1) * 32 + b_koff) ^ b_xm);
                #pragma unroll
                for (int nj = 0; nj < 4; nj++) LDSM_X4(b[cb ^ 1][nj], bw + nj * 2048 + bq);
            }
            #pragma unroll
            for (int mi = 0; mi < MI; mi++) {
                #pragma unroll
                for (int ni = 0; ni < 8; ni++)
                    MMA16816(c[mi][ni], a[mi],
                             b[cb][ni >> 1][(ni & 1) * 2], b[cb][ni >> 1][(ni & 1) * 2 + 1]);
                if (q < 3) {
                    const uint32_t aq = (uint32_t)(((q + 1) * 32 + a_koff) ^ a_xm);
                    LDSM_X4(a[mi], aw + mi * 2048 + aq);
                }
            }
        }

        CP_WAIT1();
        __syncthreads();
    }

    // fused epilogue
    const int gid = lane >> 2, tig = lane & 3;
    const float k4 = 4.0e-3f;  // 2/500

    #pragma unroll
    for (int mi = 0; mi < MI; mi++) {
        const int r0 = wm * (MI * 16) + mi * 16 + gid;
        const float xs0 = s_xsq[r0];
        const float xs1 = s_xsq[r0 + 8];
        float* o0 = out + (size_t)(bm + r0) * S_ROWS + bn;
        float* o1 = o0 + (size_t)8 * S_ROWS;
        #pragma unroll
        for (int ni = 0; ni < 8; ni++) {
            const int col = wn * 64 + ni * 8 + tig * 2;
            const float ms0 = s_msq[col];
            const float ms1 = s_msq[col + 1];
            float2 v0, v1;
            v0.x = fmaf(c[mi][ni][0], k4, xs0 + ms0);
            v0.y = fmaf(c[mi][ni][1], k4, xs0 + ms1);
            v1.x = fmaf(c[mi][ni][2], k4, xs1 + ms0);
            v1.y = fmaf(c[mi][ni][3], k4, xs1 + ms1);
            *reinterpret_cast<float2*>(o0 + col) = v0;
            *reinterpret_cast<float2*>(o1 + col) = v1;
        }
    }
}

__global__ __launch_bounds__(128, 2)
void gemm_sqdist_mma(float* __restrict__ out) {
    extern __shared__ char dyn_smem[];
    __shared__ float s_xsq[128];
    __shared__ float s_msq[128];

    const int tid = threadIdx.x;
    const int bid = blockIdx.x;
    const uint32_t dbase = (smem_to_u32(dyn_smem) + 1023u) & ~1023u;

    if (bid < N_FULL) {
        const int bm = (bid >> 4) * 128;          // rows [0, 2304)
        const int bn = (bid & 15) * BN;
        tile_body<4>(out, bm, bn, dbase, tid, s_xsq, s_msq);
    } else {
        const int h  = bid - N_FULL;              // 0..447
        const int bm = 2304 + (h >> 4) * 64;      // rows [2304, 4096)
        const int bn = (h & 15) * BN;
        tile_body<2>(out, bm, bn, dbase, tid, s_xsq, s_msq);
    }
}

// ---------------------------------------------------------------------------
extern "C" void kernel_launch(void* const* d_in, const int* in_sizes, int n_in,
                              void* d_out, int out_size) {
    const float* observation        = (const float*)d_in[0];  // [4096, 2496]
    const float* observation_matrix = (const float*)d_in[1];  // [2048, 2496]
    float* out = (float*)d_out;                                // [4096, 2048]

    const int conv_blocks = (B_ROWS + S_ROWS) / CONV_WPB;  // 768
    convert_fused<<<conv_blocks, 256>>>(observation, observation_matrix);

    const int dyn_bytes = NSTAGE * STAGE_STRIDE + 1024;  // 99328
    cudaFuncSetAttribute(gemm_sqdist_mma, cudaFuncAttributeMaxDynamicSharedMemorySize, dyn_bytes);
    gemm_sqdist_mma<<<N_FULL + N_HALF, 128, dyn_bytes>>>(out);  // 736 CTAs
}

// round 9
// speedup vs baseline: 3.4118x; 1.0176x over previous
#include <cuda_runtime.h>
#include <cuda_bf16.h>
#include <cstdint>

#define B_ROWS 4096
#define S_ROWS 2048
#define DDIM   2496

// ---------------- device scratch (allocation-free rule) ----------------
__device__ __align__(16) __nv_bfloat16 g_Xb[(size_t)B_ROWS * DDIM];
__device__ __align__(16) __nv_bfloat16 g_Mb[(size_t)S_ROWS * DDIM];
__device__ float g_xsq[B_ROWS];
__device__ float g_msq[S_ROWS];

// ---------------- helpers ----------------
__device__ __forceinline__ uint32_t smem_to_u32(const void* p) {
    uint32_t a;
    asm("{ .reg .u64 t; cvta.to.shared.u64 t, %1; cvt.u32.u64 %0, t; }" : "=r"(a) : "l"(p));
    return a;
}
#define SWZ_C(row, c) ((c) ^ (((row) & 7) << 4))   // SW128 swizzle within 128B rows

#define CP_ASYNC16(dst, src) \
    asm volatile("cp.async.cg.shared.global [%0], [%1], 16;" :: "r"(dst), "l"(src))
#define CP_COMMIT() asm volatile("cp.async.commit_group;" ::: "memory")
#define CP_WAIT1()  asm volatile("cp.async.wait_group 1;" ::: "memory")

#define LDSM_X4(r, addr) \
    asm volatile("ldmatrix.sync.aligned.m8n8.x4.shared.b16 {%0,%1,%2,%3}, [%4];" \
        : "=r"((r)[0]), "=r"((r)[1]), "=r"((r)[2]), "=r"((r)[3]) : "r"(addr))

#define MMA16816(d, a, b0, b1) \
    asm volatile("mma.sync.aligned.m16n8k16.row.col.f32.bf16.bf16.f32 " \
        "{%0,%1,%2,%3}, {%4,%5,%6,%7}, {%8,%9}, {%0,%1,%2,%3};" \
        : "+f"((d)[0]), "+f"((d)[1]), "+f"((d)[2]), "+f"((d)[3]) \
        : "r"((a)[0]), "r"((a)[1]), "r"((a)[2]), "r"((a)[3]), "r"(b0), "r"(b1))

// ---------------------------------------------------------------------------
// Fused convert: warp-per-row, both tensors in one launch.
// ---------------------------------------------------------------------------
#define CONV_WPB 8
__global__ __launch_bounds__(256, 4)
void convert_fused(const float* __restrict__ X, const float* __restrict__ M) {
    const int lane  = threadIdx.x & 31;
    const int gwarp = blockIdx.x * CONV_WPB + (threadIdx.x >> 5);

    const float* src;
    __nv_bfloat16* dst;
    float* sqv;
    if (gwarp < B_ROWS) {
        src = X + (size_t)gwarp * DDIM;
        dst = g_Xb + (size_t)gwarp * DDIM;
        sqv = &g_xsq[gwarp];
    } else {
        const int row = gwarp - B_ROWS;
        src = M + (size_t)row * DDIM;
        dst = g_Mb + (size_t)row * DDIM;
        sqv = &g_msq[row];
    }

    const float4* s4 = reinterpret_cast<const float4*>(src);
    uint2*        d2 = reinterpret_cast<uint2*>(dst);

    float acc = 0.f;
    const int n4 = DDIM / 4;  // 624
    #pragma unroll 4
    for (int i = lane; i < n4; i += 32) {
        float4 f = s4[i];
        acc = fmaf(f.x, f.x, acc);
        acc = fmaf(f.y, f.y, acc);
        acc = fmaf(f.z, f.z, acc);
        acc = fmaf(f.w, f.w, acc);
        __nv_bfloat162 lo = __floats2bfloat162_rn(f.x, f.y);
        __nv_bfloat162 hi = __floats2bfloat162_rn(f.z, f.w);
        uint2 u;
        u.x = *reinterpret_cast<unsigned int*>(&lo);
        u.y = *reinterpret_cast<unsigned int*>(&hi);
        d2[i] = u;
    }
    #pragma unroll
    for (int o = 16; o > 0; o >>= 1) acc += __shfl_down_sync(0xFFFFFFFFu, acc, o);
    if (lane == 0) *sqv = acc;
}

// ---------------------------------------------------------------------------
// Mixed-tile bf16 mma.sync GEMM:
//   bid <  288 : full tile 128x128, 4 warps 2x2, warp tile 64x64
//   bid >= 288 : half tile  64x128, 4 warps SPLIT-K (warps 0,1: k-lower half
//                of each BK=64; warps 2,3: k-upper), warp tile 64x64, fp32
//                cross-warp reduction in SMEM at the end.
// BK=64, SW128 + ldmatrix, cp.async 3 stages, register pipelining, 2 CTAs/SM.
// Epilogue: out = fmaf(dot, 4e-3, -(xsq+msq)*2e-3)
// ---------------------------------------------------------------------------
#define BN 128
#define BK 64
#define NSTAGE 3
#define NT (DDIM / BK)                   // 39
#define STAGE_STRIDE 32768
#define N_FULL 288                       // 18 x 16 tiles of 128x128
#define N_HALF 448                       // 28 x 16 tiles of  64x128

// ---------------- full tile (128x128) ----------------
__device__ __forceinline__ void tile_body_full(
    float* __restrict__ out, int bm, int bn, uint32_t dbase, int tid,
    float* s_xsq, float* s_msq)
{
    const int lane = tid & 31;
    const int warp = tid >> 5;
    const int wm   = warp & 1;
    const int wn   = warp >> 1;

    uint32_t sA[NSTAGE], sB[NSTAGE];
    #pragma unroll
    for (int s = 0; s < NSTAGE; s++) {
        sA[s] = dbase + s * STAGE_STRIDE;
        sB[s] = sA[s] + 128 * 128;
    }

    s_xsq[tid] = g_xsq[bm + tid] * -2.0e-3f;
    s_msq[tid] = g_msq[bn + tid] * -2.0e-3f;

    const __nv_bfloat16* gA = g_Xb + (size_t)bm * DDIM;
    const __nv_bfloat16* gB = g_Mb + (size_t)bn * DDIM;

    auto load_stage = [&](int kt, uint32_t dstA, uint32_t dstB) {
        const int kb = kt * 8;
        #pragma unroll
        for (int q = 0; q < 8; q++) {
            const int item = q * 128 + tid;
            const int row = item >> 3, i = item & 7;
            CP_ASYNC16(dstA + row * 128 + SWZ_C(row, i * 16),
                       gA + (size_t)row * DDIM + (size_t)(kb + i) * 8);
        }
        #pragma unroll
        for (int q = 0; q < 8; q++) {
            const int item = q * 128 + tid;
            const int row = item >> 3, i = item & 7;
            CP_ASYNC16(dstB + row * 128 + SWZ_C(row, i * 16),
                       gB + (size_t)row * DDIM + (size_t)(kb + i) * 8);
        }
    };

    const int a_row  = (lane & 7) + ((lane >> 3) & 1) * 8;
    const int a_koff = ((lane >> 4) & 1) * 16;
    const uint32_t a_base_off = (uint32_t)(wm * 64 + a_row) * 128;
    const int a_xm = (a_row & 7) << 4;
    const int b_row  = (lane & 7) + ((lane >> 4) & 1) * 8;
    const int b_koff = ((lane >> 3) & 1) * 16;
    const uint32_t b_base_off = (uint32_t)(wn * 64 + b_row) * 128;
    const int b_xm = (b_row & 7) << 4;

    float c[4][8][4];
    #pragma unroll
    for (int mi = 0; mi < 4; mi++)
        #pragma unroll
        for (int ni = 0; ni < 8; ni++)
            #pragma unroll
            for (int e = 0; e < 4; e++) c[mi][ni][e] = 0.f;

    load_stage(0, sA[0], sB[0]); CP_COMMIT();
    load_stage(1, sA[1], sB[1]); CP_COMMIT();
    CP_WAIT1();
    __syncthreads();

    #pragma unroll 3
    for (int kt = 0; kt < NT; kt++) {
        const int buf = kt % NSTAGE;
        if (kt + 2 < NT) {
            const int nb = (kt + 2) % NSTAGE;
            load_stage(kt + 2, sA[nb], sB[nb]);
        }
        CP_COMMIT();

        const uint32_t aw = sA[buf] + a_base_off;
        const uint32_t bw = sB[buf] + b_base_off;

        uint32_t a[4][4];
        uint32_t b[2][4][4];
        {
            const uint32_t aq = (uint32_t)(a_koff ^ a_xm);
            const uint32_t bq = (uint32_t)(b_koff ^ b_xm);
            #pragma unroll
            for (int mi = 0; mi < 4; mi++) LDSM_X4(a[mi], aw + mi * 2048 + aq);
            #pragma unroll
            for (int nj = 0; nj < 4; nj++) LDSM_X4(b[0][nj], bw + nj * 2048 + bq);
        }
        #pragma unroll
        for (int q = 0; q < 4; q++) {
            const int cb = q & 1;
            if (q < 3) {
                const uint32_t bq = (uint32_t)(((q + 1) * 32 + b_koff) ^ b_xm);
                #pragma unroll
                for (int nj = 0; nj < 4; nj++) LDSM_X4(b[cb ^ 1][nj], bw + nj * 2048 + bq);
            }
            #pragma unroll
            for (int mi = 0; mi < 4; mi++) {
                #pragma unroll
                for (int ni = 0; ni < 8; ni++)
                    MMA16816(c[mi][ni], a[mi],
                             b[cb][ni >> 1][(ni & 1) * 2], b[cb][ni >> 1][(ni & 1) * 2 + 1]);
                if (q < 3) {
                    const uint32_t aq = (uint32_t)(((q + 1) * 32 + a_koff) ^ a_xm);
                    LDSM_X4(a[mi], aw + mi * 2048 + aq);
                }
            }
        }

        CP_WAIT1();
        __syncthreads();
    }

    const int gid = lane >> 2, tig = lane & 3;
    const float k4 = 4.0e-3f;
    #pragma unroll
    for (int mi = 0; mi < 4; mi++) {
        const int r0 = wm * 64 + mi * 16 + gid;
        const float xs0 = s_xsq[r0];
        const float xs1 = s_xsq[r0 + 8];
        float* o0 = out + (size_t)(bm + r0) * S_ROWS + bn;
        float* o1 = o0 + (size_t)8 * S_ROWS;
        #pragma unroll
        for (int ni = 0; ni < 8; ni++) {
            const int col = wn * 64 + ni * 8 + tig * 2;
            const float ms0 = s_msq[col];
            const float ms1 = s_msq[col + 1];
            float2 v0, v1;
            v0.x = fmaf(c[mi][ni][0], k4, xs0 + ms0);
            v0.y = fmaf(c[mi][ni][1], k4, xs0 + ms1);
            v1.x = fmaf(c[mi][ni][2], k4, xs1 + ms0);
            v1.y = fmaf(c[mi][ni][3], k4, xs1 + ms1);
            *reinterpret_cast<float2*>(o0 + col) = v0;
            *reinterpret_cast<float2*>(o1 + col) = v1;
        }
    }
}

// ---------------- half tile (64x128, intra-CTA split-K) ----------------
__device__ __forceinline__ void tile_body_half(
    float* __restrict__ out, int bm, int bn, uint32_t dbase, float* stagef,
    int tid, float* s_xsq, float* s_msq)
{
    const int lane = tid & 31;
    const int warp = tid >> 5;
    const int wn   = warp & 1;   // N half: cols [wn*64, wn*64+64)
    const int kg   = warp >> 1;  // k-group: 0 -> q{0,1}, 1 -> q{2,3}

    uint32_t sA[NSTAGE], sB[NSTAGE];
    #pragma unroll
    for (int s = 0; s < NSTAGE; s++) {
        sA[s] = dbase + s * STAGE_STRIDE;
        sB[s] = sA[s] + 64 * 128;
    }

    if (tid < 64) s_xsq[tid] = g_xsq[bm + tid] * -2.0e-3f;
    s_msq[tid] = g_msq[bn + tid] * -2.0e-3f;

    const __nv_bfloat16* gA = g_Xb + (size_t)bm * DDIM;
    const __nv_bfloat16* gB = g_Mb + (size_t)bn * DDIM;

    auto load_stage = [&](int kt, uint32_t dstA, uint32_t dstB) {
        const int kb = kt * 8;
        #pragma unroll
        for (int q = 0; q < 4; q++) {           // A: 64 rows x 8 chunks
            const int item = q * 128 + tid;
            const int row = item >> 3, i = item & 7;
            CP_ASYNC16(dstA + row * 128 + SWZ_C(row, i * 16),
                       gA + (size_t)row * DDIM + (size_t)(kb + i) * 8);
        }
        #pragma unroll
        for (int q = 0; q < 8; q++) {           // B: 128 rows x 8 chunks
            const int item = q * 128 + tid;
            const int row = item >> 3, i = item & 7;
            CP_ASYNC16(dstB + row * 128 + SWZ_C(row, i * 16),
                       gB + (size_t)row * DDIM + (size_t)(kb + i) * 8);
        }
    };

    const int a_row  = (lane & 7) + ((lane >> 3) & 1) * 8;
    const int a_koff = ((lane >> 4) & 1) * 16;
    const uint32_t a_base_off = (uint32_t)a_row * 128;   // all warps: rows 0-63
    const int a_xm = (a_row & 7) << 4;
    const int b_row  = (lane & 7) + ((lane >> 4) & 1) * 8;
    const int b_koff = ((lane >> 3) & 1) * 16;
    const uint32_t b_base_off = (uint32_t)(wn * 64 + b_row) * 128;
    const int b_xm = (b_row & 7) << 4;

    const int kbyte0 = kg * 64;   // this warp's first k16-step byte offset

    float c[4][8][4];
    #pragma unroll
    for (int mi = 0; mi < 4; mi++)
        #pragma unroll
        for (int ni = 0; ni < 8; ni++)
            #pragma unroll
            for (int e = 0; e < 4; e++) c[mi][ni][e] = 0.f;

    load_stage(0, sA[0], sB[0]); CP_COMMIT();
    load_stage(1, sA[1], sB[1]); CP_COMMIT();
    CP_WAIT1();
    __syncthreads();

    #pragma unroll 3
    for (int kt = 0; kt < NT; kt++) {
        const int buf = kt % NSTAGE;
        if (kt + 2 < NT) {
            const int nb = (kt + 2) % NSTAGE;
            load_stage(kt + 2, sA[nb], sB[nb]);
        }
        CP_COMMIT();

        const uint32_t aw = sA[buf] + a_base_off;
        const uint32_t bw = sB[buf] + b_base_off;

        uint32_t a[4][4];
        uint32_t b[2][4][4];
        {   // qq = 0 preload (this warp's lower k16)
            const uint32_t aq = (uint32_t)((kbyte0 + a_koff) ^ a_xm);
            const uint32_t bq = (uint32_t)((kbyte0 + b_koff) ^ b_xm);
            #pragma unroll
            for (int mi = 0; mi < 4; mi++) LDSM_X4(a[mi], aw + mi * 2048 + aq);
            #pragma unroll
            for (int nj = 0; nj < 4; nj++) LDSM_X4(b[0][nj], bw + nj * 2048 + bq);
        }
        {   // prefetch qq = 1 B frags
            const uint32_t bq = (uint32_t)((kbyte0 + 32 + b_koff) ^ b_xm);
            #pragma unroll
            for (int nj = 0; nj < 4; nj++) LDSM_X4(b[1][nj], bw + nj * 2048 + bq);
        }
        // qq = 0 MMAs + JIT A reload for qq = 1
        #pragma unroll
        for (int mi = 0; mi < 4; mi++) {
            #pragma unroll
            for (int ni = 0; ni < 8; ni++)
                MMA16816(c[mi][ni], a[mi],
                         b[0][ni >> 1][(ni & 1) * 2], b[0][ni >> 1][(ni & 1) * 2 + 1]);
            const uint32_t aq = (uint32_t)((kbyte0 + 32 + a_koff) ^ a_xm);
            LDSM_X4(a[mi], aw + mi * 2048 + aq);
        }
        // qq = 1 MMAs
        #pragma unroll
        for (int mi = 0; mi < 4; mi++)
            #pragma unroll
            for (int ni = 0; ni < 8; ni++)
                MMA16816(c[mi][ni], a[mi],
                         b[1][ni >> 1][(ni & 1) * 2], b[1][ni >> 1][(ni & 1) * 2 + 1]);

        CP_WAIT1();
        __syncthreads();
    }

    // ---- cross-warp split-K reduction ----
    // kg==1 warps stage their accumulators; kg==0 warps add + fused epilogue.
    if (kg == 1) {
        float* st = stagef + wn * 4096 + lane * 4;
        #pragma unroll
        for (int mi = 0; mi < 4; mi++)
            #pragma unroll
            for (int ni = 0; ni < 8; ni++)
                *reinterpret_cast<float4*>(st + (mi * 8 + ni) * 128) =
                    *reinterpret_cast<const float4*>(c[mi][ni]);
    }
    __syncthreads();

    if (kg == 0) {
        const float* st = stagef + wn * 4096 + lane * 4;
        const int gid = lane >> 2, tig = lane & 3;
        const float k4 = 4.0e-3f;
        #pragma unroll
        for (int mi = 0; mi < 4; mi++) {
            const int r0 = mi * 16 + gid;
            const float xs0 = s_xsq[r0];
            const float xs1 = s_xsq[r0 + 8];
            float* o0 = out + (size_t)(bm + r0) * S_ROWS + bn;
            float* o1 = o0 + (size_t)8 * S_ROWS;
            #pragma unroll
            for (int ni = 0; ni < 8; ni++) {
                const float4 p = *reinterpret_cast<const float4*>(st + (mi * 8 + ni) * 128);
                const int col = wn * 64 + ni * 8 + tig * 2;
                const float ms0 = s_msq[col];
                const float ms1 = s_msq[col + 1];
                float2 v0, v1;
                v0.x = fmaf(c[mi][ni][0] + p.x, k4, xs0 + ms0);
                v0.y = fmaf(c[mi][ni][1] + p.y, k4, xs0 + ms1);
                v1.x = fmaf(c[mi][ni][2] + p.z, k4, xs1 + ms0);
                v1.y = fmaf(c[mi][ni][3] + p.w, k4, xs1 + ms1);
                *reinterpret_cast<float2*>(o0 + col) = v0;
                *reinterpret_cast<float2*>(o1 + col) = v1;
            }
        }
    }
}

__global__ __launch_bounds__(128, 2)
void gemm_sqdist_mma(float* __restrict__ out) {
    extern __shared__ char dyn_smem[];
    __shared__ float s_xsq[128];
    __shared__ float s_msq[128];

    const int tid = threadIdx.x;
    const int bid = blockIdx.x;
    char* dptr = dyn_smem + (((~(uintptr_t)dyn_smem) + 1) & 1023);  // 1KB align
    const uint32_t dbase = smem_to_u32(dptr);

    if (bid < N_FULL) {
        const int bm = (bid >> 4) * 128;          // rows [0, 2304)
        const int bn = (bid & 15) * BN;
        tile_body_full(out, bm, bn, dbase, tid, s_xsq, s_msq);
    } else {
        const int h  = bid - N_FULL;              // 0..447
        const int bm = 2304 + (h >> 4) * 64;      // rows [2304, 4096)
        const int bn = (h & 15) * BN;
        tile_body_half(out, bm, bn, dbase, reinterpret_cast<float*>(dptr),
                       tid, s_xsq, s_msq);
    }
}

// ---------------------------------------------------------------------------
extern "C" void kernel_launch(void* const* d_in, const int* in_sizes, int n_in,
                              void* d_out, int out_size) {
    const float* observation        = (const float*)d_in[0];  // [4096, 2496]
    const float* observation_matrix = (const float*)d_in[1];  // [2048, 2496]
    float* out = (float*)d_out;                                // [4096, 2048]

    const int conv_blocks = (B_ROWS + S_ROWS) / CONV_WPB;  // 768
    convert_fused<<<conv_blocks, 256>>>(observation, observation_matrix);

    const int dyn_bytes = NSTAGE * STAGE_STRIDE + 1024;  // 99328
    cudaFuncSetAttribute(gemm_sqdist_mma, cudaFuncAttributeMaxDynamicSharedMemorySize, dyn_bytes);
    gemm_sqdist_mma<<<N_FULL + N_HALF, 128, dyn_bytes>>>(out);  // 736 CTAs
}